// round 1
// baseline (speedup 1.0000x reference)
#include <cuda_runtime.h>
#include <cstddef>

// ---------------------------------------------------------------------------
// MultiHeadAttention: x@W_attn+b -> causal MHA -> @W_proj+b
// B=2, T=2048, C=1024, H=16, D=64.  All fp32 (round-1 baseline).
// ---------------------------------------------------------------------------

#define BB 2
#define TT 2048
#define CC 1024
#define NH 16
#define HD 64

// scratch (no cudaMalloc allowed)
__device__ float g_qkv[BB * TT * 3 * CC];  // [B*T, 3C] row-major
__device__ float g_y[BB * TT * CC];        // [B*T, C]  row-major (B,T,H,D)

// ---------------------------------------------------------------------------
// SGEMM: C[M,N] = A[M,K] @ B[K,N] + bias[N]
// 128x128 block tile, BK=8, 256 threads, 8x8 microtile.
// M,N multiples of 128; K multiple of 8.
// ---------------------------------------------------------------------------
__global__ __launch_bounds__(256) void sgemm_bias_kernel(
    const float* __restrict__ A, const float* __restrict__ B,
    const float* __restrict__ bias, float* __restrict__ C,
    int M, int N, int K)
{
    __shared__ float As[8][128];  // As[k][m]
    __shared__ float Bs[8][128];  // Bs[k][n]

    const int tid = threadIdx.x;
    const int ty = tid >> 4;      // 0..15
    const int tx = tid & 15;      // 0..15
    const int m0 = blockIdx.y * 128;
    const int n0 = blockIdx.x * 128;

    float acc[8][8];
#pragma unroll
    for (int i = 0; i < 8; ++i)
#pragma unroll
        for (int j = 0; j < 8; ++j) acc[i][j] = 0.f;

    const int arow = tid >> 1;          // 0..127
    const int acol = (tid & 1) << 2;    // 0 or 4
    const int brow = tid >> 5;          // 0..7
    const int bcol = (tid & 31) << 2;   // 0..124

    const float* Ap = A + (size_t)(m0 + arow) * K + acol;
    const float* Bp = B + (size_t)brow * N + n0 + bcol;

    for (int k0 = 0; k0 < K; k0 += 8) {
        float4 av = *(const float4*)(Ap + k0);
        float4 bv = *(const float4*)(Bp + (size_t)k0 * N);
        As[acol + 0][arow] = av.x;
        As[acol + 1][arow] = av.y;
        As[acol + 2][arow] = av.z;
        As[acol + 3][arow] = av.w;
        *(float4*)&Bs[brow][bcol] = bv;
        __syncthreads();

#pragma unroll
        for (int k = 0; k < 8; ++k) {
            float a[8], b[8];
            *(float4*)&a[0] = *(const float4*)&As[k][ty * 8];
            *(float4*)&a[4] = *(const float4*)&As[k][ty * 8 + 4];
            *(float4*)&b[0] = *(const float4*)&Bs[k][tx * 8];
            *(float4*)&b[4] = *(const float4*)&Bs[k][tx * 8 + 4];
#pragma unroll
            for (int i = 0; i < 8; ++i)
#pragma unroll
                for (int j = 0; j < 8; ++j)
                    acc[i][j] = fmaf(a[i], b[j], acc[i][j]);
        }
        __syncthreads();
    }

#pragma unroll
    for (int i = 0; i < 8; ++i) {
        const size_t m = (size_t)(m0 + ty * 8 + i);
#pragma unroll
        for (int j = 0; j < 8; j += 4) {
            const int n = n0 + tx * 8 + j;
            float4 o;
            o.x = acc[i][j + 0] + bias[n + 0];
            o.y = acc[i][j + 1] + bias[n + 1];
            o.z = acc[i][j + 2] + bias[n + 2];
            o.w = acc[i][j + 3] + bias[n + 3];
            *(float4*)&C[m * N + n] = o;
        }
    }
}

// ---------------------------------------------------------------------------
// Flash attention (fp32, causal, online softmax).
// CTA: 128 queries of one (b,h). 256 threads as 16(ty) x 16(tx).
// Thread owns 8 query rows (ty*8..) x 4 cols.
// Softmax rows live in one half-warp -> shuffle reductions, no smem.
// Dynamic smem 96KB: QT[64][128] | PT[64][128] | KT[64][64] | V[64][64]
// ---------------------------------------------------------------------------
__global__ __launch_bounds__(256, 2) void flash_attn_kernel(
    const float* __restrict__ qkv, float* __restrict__ y)
{
    extern __shared__ float sm[];
    float* sQT = sm;                           // [64][128]
    float* sPT = sm + 64 * 128;                // [64][128]
    float* sKT = sm + 2 * 64 * 128;            // [64][64]
    float* sV  = sm + 2 * 64 * 128 + 64 * 64;  // [64][64]

    const int tid = threadIdx.x;
    const int ty = tid >> 4;
    const int tx = tid & 15;
    const int qt = (int)gridDim.x - 1 - (int)blockIdx.x;  // heavy tiles first
    const int bh = blockIdx.y;
    const int b = bh >> 4;
    const int h = bh & 15;

    const float* Qg = qkv + ((size_t)b * TT + (size_t)qt * 128) * (3 * CC) + h * HD;
    const float* Kg = qkv + (size_t)b * TT * (3 * CC) + CC + h * HD;
    const float* Vg = Kg + CC;

    // Load Q tile transposed + pre-scaled by 1/sqrt(D)
    {
        const int r = tid >> 1;              // 0..127
        const int d0 = (tid & 1) << 5;       // 0 or 32
        const float* qp = Qg + (size_t)r * (3 * CC) + d0;
#pragma unroll
        for (int j = 0; j < 8; ++j) {
            float4 v = *(const float4*)(qp + j * 4);
            const int d = d0 + j * 4;
            sQT[(d + 0) * 128 + r] = v.x * 0.125f;
            sQT[(d + 1) * 128 + r] = v.y * 0.125f;
            sQT[(d + 2) * 128 + r] = v.z * 0.125f;
            sQT[(d + 3) * 128 + r] = v.w * 0.125f;
        }
    }

    float m_run[8], l_run[8], o[8][4];
#pragma unroll
    for (int i = 0; i < 8; ++i) {
        m_run[i] = -1e30f;
        l_run[i] = 0.f;
#pragma unroll
        for (int j = 0; j < 4; ++j) o[i][j] = 0.f;
    }

    const int nkt = 2 * qt + 2;  // causal: key tiles 0 .. 2*qt+1
    for (int kt = 0; kt < nkt; ++kt) {
        __syncthreads();  // protect sKT/sV/sPT from previous iteration readers
        {
            const int r = tid >> 2;            // 0..63
            const int d0 = (tid & 3) << 4;     // 0,16,32,48
            const float* kp = Kg + (size_t)(kt * 64 + r) * (3 * CC) + d0;
            const float* vp = Vg + (size_t)(kt * 64 + r) * (3 * CC) + d0;
#pragma unroll
            for (int j = 0; j < 4; ++j) {
                float4 kv = *(const float4*)(kp + j * 4);
                const int d = d0 + j * 4;
                sKT[(d + 0) * 64 + r] = kv.x;
                sKT[(d + 1) * 64 + r] = kv.y;
                sKT[(d + 2) * 64 + r] = kv.z;
                sKT[(d + 3) * 64 + r] = kv.w;
                *(float4*)&sV[r * 64 + d0 + j * 4] = *(const float4*)(vp + j * 4);
            }
        }
        __syncthreads();

        // S = Q @ K^T (pre-scaled)
        float s[8][4];
#pragma unroll
        for (int i = 0; i < 8; ++i)
#pragma unroll
            for (int j = 0; j < 4; ++j) s[i][j] = 0.f;

#pragma unroll 8
        for (int d = 0; d < 64; ++d) {
            float q8[8], k4[4];
            *(float4*)&q8[0] = *(const float4*)&sQT[d * 128 + ty * 8];
            *(float4*)&q8[4] = *(const float4*)&sQT[d * 128 + ty * 8 + 4];
            *(float4*)&k4[0] = *(const float4*)&sKT[d * 64 + tx * 4];
#pragma unroll
            for (int i = 0; i < 8; ++i)
#pragma unroll
                for (int j = 0; j < 4; ++j)
                    s[i][j] = fmaf(q8[i], k4[j], s[i][j]);
        }

        // causal mask (only diagonal-region tiles)
        if (kt >= 2 * qt) {
#pragma unroll
            for (int i = 0; i < 8; ++i) {
                const int qrow = qt * 128 + ty * 8 + i;
#pragma unroll
                for (int j = 0; j < 4; ++j) {
                    const int kcol = kt * 64 + tx * 4 + j;
                    if (kcol > qrow) s[i][j] = -1e30f;
                }
            }
        }

        // online softmax; row = 16 lanes of a half-warp -> shuffle reduce
#pragma unroll
        for (int i = 0; i < 8; ++i) {
            float mx = fmaxf(fmaxf(s[i][0], s[i][1]), fmaxf(s[i][2], s[i][3]));
#pragma unroll
            for (int off = 1; off < 16; off <<= 1)
                mx = fmaxf(mx, __shfl_xor_sync(0xffffffffu, mx, off));
            const float mnew = fmaxf(m_run[i], mx);
            const float alpha = __expf(m_run[i] - mnew);
            float rs = 0.f;
#pragma unroll
            for (int j = 0; j < 4; ++j) {
                s[i][j] = __expf(s[i][j] - mnew);
                rs += s[i][j];
            }
#pragma unroll
            for (int off = 1; off < 16; off <<= 1)
                rs += __shfl_xor_sync(0xffffffffu, rs, off);
            m_run[i] = mnew;
            l_run[i] = l_run[i] * alpha + rs;
#pragma unroll
            for (int j = 0; j < 4; ++j) o[i][j] *= alpha;
        }

        // stage P transposed: sPT[k][r]
#pragma unroll
        for (int j = 0; j < 4; ++j) {
            float4 p0 = make_float4(s[0][j], s[1][j], s[2][j], s[3][j]);
            float4 p1 = make_float4(s[4][j], s[5][j], s[6][j], s[7][j]);
            *(float4*)&sPT[(tx * 4 + j) * 128 + ty * 8] = p0;
            *(float4*)&sPT[(tx * 4 + j) * 128 + ty * 8 + 4] = p1;
        }
        __syncthreads();

        // O += P @ V
#pragma unroll 8
        for (int k = 0; k < 64; ++k) {
            float p8[8], v4[4];
            *(float4*)&p8[0] = *(const float4*)&sPT[k * 128 + ty * 8];
            *(float4*)&p8[4] = *(const float4*)&sPT[k * 128 + ty * 8 + 4];
            *(float4*)&v4[0] = *(const float4*)&sV[k * 64 + tx * 4];
#pragma unroll
            for (int i = 0; i < 8; ++i)
#pragma unroll
                for (int j = 0; j < 4; ++j)
                    o[i][j] = fmaf(p8[i], v4[j], o[i][j]);
        }
    }

    // epilogue: normalize, write y[B,T,H*D]
#pragma unroll
    for (int i = 0; i < 8; ++i) {
        const float inv = 1.0f / l_run[i];
        const int row = qt * 128 + ty * 8 + i;
        float4 out = make_float4(o[i][0] * inv, o[i][1] * inv,
                                 o[i][2] * inv, o[i][3] * inv);
        *(float4*)&y[((size_t)b * TT + row) * CC + h * HD + tx * 4] = out;
    }
}

// ---------------------------------------------------------------------------
// launch
// ---------------------------------------------------------------------------
extern "C" void kernel_launch(void* const* d_in, const int* in_sizes, int n_in,
                              void* d_out, int out_size)
{
    (void)in_sizes; (void)n_in; (void)out_size;
    const float* x      = (const float*)d_in[0];
    const float* W_attn = (const float*)d_in[1];
    const float* b_attn = (const float*)d_in[2];
    const float* W_proj = (const float*)d_in[3];
    const float* b_proj = (const float*)d_in[4];
    float* out = (float*)d_out;

    float* qkv = nullptr;
    float* yb  = nullptr;
    cudaGetSymbolAddress((void**)&qkv, g_qkv);
    cudaGetSymbolAddress((void**)&yb, g_y);

    // opt-in to 96KB dynamic smem for the attention kernel (idempotent)
    cudaFuncSetAttribute(flash_attn_kernel,
                         cudaFuncAttributeMaxDynamicSharedMemorySize, 96 * 1024);

    // 1) QKV = x @ W_attn + b_attn          [4096,1024]x[1024,3072]
    {
        dim3 grid(3 * CC / 128, BB * TT / 128);  // (24, 32)
        sgemm_bias_kernel<<<grid, 256>>>(x, W_attn, b_attn, qkv,
                                         BB * TT, 3 * CC, CC);
    }
    // 2) y = causal_softmax(Q K^T / sqrt(D)) V
    {
        dim3 grid(TT / 128, BB * NH);  // (16, 32)
        flash_attn_kernel<<<grid, 256, 96 * 1024>>>(qkv, yb);
    }
    // 3) out = y @ W_proj + b_proj          [4096,1024]x[1024,1024]
    {
        dim3 grid(CC / 128, BB * TT / 128);  // (8, 32)
        sgemm_bias_kernel<<<grid, 256>>>(yb, W_proj, b_proj, out,
                                         BB * TT, CC, CC);
    }
}

// round 4
// speedup vs baseline: 1.3581x; 1.3581x over previous
#include <cuda_runtime.h>
#include <cuda_bf16.h>
#include <cstdint>
#include <cstddef>

// ---------------------------------------------------------------------------
// MultiHeadAttention: x@W_attn+b -> causal MHA -> @W_proj+b
// B=2, T=2048, C=1024, H=16, D=64.
// Round 4 (= R3 resubmit + 4-stage pipeline): GEMMs via mma.sync bf16 hi/lo
// split (K-tripled); attention fp32.
// ---------------------------------------------------------------------------

#define BB 2
#define TT 2048
#define CC 1024
#define NH 16
#define HD 64
#define MTOT (BB * TT)  // 4096
#define K3 (3 * CC)     // 3072 (tripled K for split GEMM)

// ------------------------------ scratch ------------------------------------
__device__ float g_qkv[BB * TT * 3 * CC];       // [B*T, 3C] fp32
__device__ float g_y[BB * TT * CC];             // [B*T, C]  fp32
__device__ __nv_bfloat16 g_a3[MTOT * K3];       // [M][3K]  = [hi | hi | lo]
__device__ __nv_bfloat16 g_wa3[3 * CC * K3];    // W_attn^T [3C][3K] = [hi | lo | hi]
__device__ __nv_bfloat16 g_wp3[CC * K3];        // W_proj^T [C][3K]  = [hi | lo | hi]

// ------------------------------ helpers ------------------------------------
__device__ __forceinline__ uint32_t smem_u32(const void* p) {
    uint32_t a;
    asm("{ .reg .u64 t; cvta.to.shared.u64 t, %1; cvt.u32.u64 %0, t; }"
        : "=r"(a) : "l"(p));
    return a;
}
__device__ __forceinline__ uint32_t swz(uint32_t x) {  // SW128
    return x ^ ((x >> 3) & 0x70);
}
__device__ __forceinline__ void cp16(uint32_t dst, const void* src) {
    asm volatile("cp.async.cg.shared.global [%0], [%1], 16;"
                 :: "r"(dst), "l"(src));
}
__device__ __forceinline__ void cp_commit() {
    asm volatile("cp.async.commit_group;");
}
template <int N>
__device__ __forceinline__ void cp_wait() {
    asm volatile("cp.async.wait_group %0;" :: "n"(N));
}
__device__ __forceinline__ void ldsm4(uint32_t& r0, uint32_t& r1, uint32_t& r2,
                                      uint32_t& r3, uint32_t addr) {
    asm volatile("ldmatrix.sync.aligned.m8n8.x4.shared.b16 {%0,%1,%2,%3}, [%4];"
                 : "=r"(r0), "=r"(r1), "=r"(r2), "=r"(r3) : "r"(addr));
}
__device__ __forceinline__ void mma16816(float* c, const uint32_t* a,
                                         const uint32_t* b) {
    asm volatile(
        "mma.sync.aligned.m16n8k16.row.col.f32.bf16.bf16.f32 "
        "{%0,%1,%2,%3}, {%4,%5,%6,%7}, {%8,%9}, {%0,%1,%2,%3};"
        : "+f"(c[0]), "+f"(c[1]), "+f"(c[2]), "+f"(c[3])
        : "r"(a[0]), "r"(a[1]), "r"(a[2]), "r"(a[3]), "r"(b[0]), "r"(b[1]));
}

// ---------------------------------------------------------------------------
// convert_split3: X [M][K] fp32 -> A3 [M][3K] bf16 = [hi | hi | lo]
// ---------------------------------------------------------------------------
__global__ __launch_bounds__(256) void convert_split3_kernel(
    const float* __restrict__ X, __nv_bfloat16* __restrict__ A3, int n4)
{
    int i = blockIdx.x * blockDim.x + threadIdx.x;
    if (i >= n4) return;
    const int m = i >> 8;             // K/4 = 256
    const int kk = (i & 255) << 2;
    float4 v = ((const float4*)X)[i];
    float vv[4] = {v.x, v.y, v.z, v.w};
    __nv_bfloat16 h[4], l[4];
#pragma unroll
    for (int j = 0; j < 4; ++j) {
        h[j] = __float2bfloat16(vv[j]);
        l[j] = __float2bfloat16(vv[j] - __bfloat162float(h[j]));
    }
    __nv_bfloat162 h0(h[0], h[1]), h1(h[2], h[3]);
    __nv_bfloat162 l0(l[0], l[1]), l1(l[2], l[3]);
    __nv_bfloat162* p0 = (__nv_bfloat162*)(A3 + (size_t)m * K3 + kk);
    p0[0] = h0; p0[1] = h1;                       // block 0: hi
    __nv_bfloat162* p1 = (__nv_bfloat162*)(A3 + (size_t)m * K3 + CC + kk);
    p1[0] = h0; p1[1] = h1;                       // block 1: hi
    __nv_bfloat162* p2 = (__nv_bfloat162*)(A3 + (size_t)m * K3 + 2 * CC + kk);
    p2[0] = l0; p2[1] = l1;                       // block 2: lo
}

// ---------------------------------------------------------------------------
// transpose_split3: W [K][N] fp32 -> B3 [N][3K] bf16 = [hi | lo | hi]
// ---------------------------------------------------------------------------
__global__ __launch_bounds__(256) void transpose_split3_kernel(
    const float* __restrict__ W, __nv_bfloat16* __restrict__ B3, int K, int N)
{
    __shared__ float t[32][33];
    const int n0 = blockIdx.x * 32, k0 = blockIdx.y * 32;
    const int tx = threadIdx.x, ty = threadIdx.y;
#pragma unroll
    for (int i = 0; i < 32; i += 8)
        t[ty + i][tx] = W[(size_t)(k0 + ty + i) * N + n0 + tx];
    __syncthreads();
#pragma unroll
    for (int i = 0; i < 32; i += 8) {
        const int n = n0 + ty + i, k = k0 + tx;
        const float v = t[tx][ty + i];
        const __nv_bfloat16 h = __float2bfloat16(v);
        const __nv_bfloat16 l = __float2bfloat16(v - __bfloat162float(h));
        __nv_bfloat16* row = B3 + (size_t)n * (3 * K);
        row[k] = h;              // block 0: hi
        row[K + k] = l;          // block 1: lo
        row[2 * K + k] = h;      // block 2: hi
    }
}

// ---------------------------------------------------------------------------
// mma.sync bf16 GEMM: C[M,N] = A3[M,K'] @ B3[N,K']^T + bias   (K' = K3)
// CTA 128x128, BK=64, 4-stage cp.async pipeline, 8 warps (2x4), warp 64x32.
// ---------------------------------------------------------------------------
#define BKB 128           // bytes per smem row (64 bf16)
#define TILE_A 16384      // 128 rows x 128B
#define STAGE 32768       // A + B
#define NSTAGE 4

__global__ __launch_bounds__(256) void gemm_mma_kernel(
    const __nv_bfloat16* __restrict__ A3, const __nv_bfloat16* __restrict__ B3,
    const float* __restrict__ bias, float* __restrict__ Cout, int N)
{
    extern __shared__ char dsm[];
    const uint32_t sbase = smem_u32(dsm);

    const int tid = threadIdx.x;
    const int lane = tid & 31;
    const int warp = tid >> 5;
    const int wm = warp >> 2;         // 0..1
    const int wn = warp & 3;          // 0..3
    const int n0 = blockIdx.x * 128;
    const int m0 = blockIdx.y * 128;

    // cp.async mapping: row = tid>>1 (0..127), 4 x 16B chunks per thread
    const int ldrow = tid >> 1;
    const int cgrp = (tid & 1) * 4;
    const __nv_bfloat16* aRow = A3 + (size_t)(m0 + ldrow) * K3 + cgrp * 8;
    const __nv_bfloat16* bRow = B3 + (size_t)(n0 + ldrow) * K3 + cgrp * 8;
    uint32_t dstOff[4];
#pragma unroll
    for (int j = 0; j < 4; ++j)
        dstOff[j] = swz(ldrow * BKB + (cgrp + j) * 16);

    const int NCH = K3 / 64;  // 48

#pragma unroll
    for (int c = 0; c < NSTAGE - 1; ++c) {  // prologue
        const uint32_t sA = sbase + c * STAGE;
        const uint32_t sB = sA + TILE_A;
#pragma unroll
        for (int j = 0; j < 4; ++j) {
            cp16(sA + dstOff[j], aRow + c * 64 + j * 8);
            cp16(sB + dstOff[j], bRow + c * 64 + j * 8);
        }
        cp_commit();
    }

    float acc[4][4][4];
#pragma unroll
    for (int i = 0; i < 4; ++i)
#pragma unroll
        for (int j = 0; j < 4; ++j)
#pragma unroll
            for (int r = 0; r < 4; ++r) acc[i][j][r] = 0.f;

    // per-lane ldmatrix address pieces
    const int arow = wm * 64 + (lane & 15);           // + fm*16
    const uint32_t acolbase = (lane >> 4) << 4;       // 0 or 16
    const int brow = wn * 32 + ((lane >> 4) << 3) + (lane & 7);  // + fn2*16
    const uint32_t bcolbase = ((lane >> 3) & 1) << 4;

    for (int c = 0; c < NCH; ++c) {
        cp_wait<NSTAGE - 2>();
        __syncthreads();

        // issue loads for chunk c + NSTAGE-1
        if (c + NSTAGE - 1 < NCH) {
            const int cc = c + NSTAGE - 1;
            const int s = cc % NSTAGE;
            const uint32_t sA = sbase + s * STAGE;
            const uint32_t sB = sA + TILE_A;
#pragma unroll
            for (int j = 0; j < 4; ++j) {
                cp16(sA + dstOff[j], aRow + cc * 64 + j * 8);
                cp16(sB + dstOff[j], bRow + cc * 64 + j * 8);
            }
        }
        cp_commit();

        const int s = c % NSTAGE;
        const uint32_t sA = sbase + s * STAGE;
        const uint32_t sB = sA + TILE_A;

#pragma unroll
        for (int kk = 0; kk < 4; ++kk) {
            uint32_t af[4][4], bf[2][4];
#pragma unroll
            for (int fm = 0; fm < 4; ++fm) {
                const int r = arow + fm * 16;
                const uint32_t addr =
                    sA + swz((uint32_t)r * BKB + kk * 32 + acolbase);
                ldsm4(af[fm][0], af[fm][1], af[fm][2], af[fm][3], addr);
            }
#pragma unroll
            for (int fn2 = 0; fn2 < 2; ++fn2) {
                const int r = brow + fn2 * 16;
                const uint32_t addr =
                    sB + swz((uint32_t)r * BKB + kk * 32 + bcolbase);
                ldsm4(bf[fn2][0], bf[fn2][1], bf[fn2][2], bf[fn2][3], addr);
            }
#pragma unroll
            for (int fm = 0; fm < 4; ++fm) {
#pragma unroll
                for (int fn = 0; fn < 4; ++fn) {
                    mma16816(acc[fm][fn], af[fm], &bf[fn >> 1][(fn & 1) * 2]);
                }
            }
        }
        __syncthreads();
    }

    // epilogue
#pragma unroll
    for (int fm = 0; fm < 4; ++fm) {
        const int r = m0 + wm * 64 + fm * 16 + (lane >> 2);
#pragma unroll
        for (int fn = 0; fn < 4; ++fn) {
            const int cidx = n0 + wn * 32 + fn * 8 + (lane & 3) * 2;
            const float b0 = bias[cidx], b1 = bias[cidx + 1];
            float2 v0 = make_float2(acc[fm][fn][0] + b0, acc[fm][fn][1] + b1);
            float2 v1 = make_float2(acc[fm][fn][2] + b0, acc[fm][fn][3] + b1);
            *(float2*)&Cout[(size_t)r * N + cidx] = v0;
            *(float2*)&Cout[(size_t)(r + 8) * N + cidx] = v1;
        }
    }
}

// ---------------------------------------------------------------------------
// Flash attention (fp32, causal, online softmax) — unchanged from round 1.
// ---------------------------------------------------------------------------
__global__ __launch_bounds__(256, 2) void flash_attn_kernel(
    const float* __restrict__ qkv, float* __restrict__ y)
{
    extern __shared__ float sm[];
    float* sQT = sm;                           // [64][128]
    float* sPT = sm + 64 * 128;                // [64][128]
    float* sKT = sm + 2 * 64 * 128;            // [64][64]
    float* sV  = sm + 2 * 64 * 128 + 64 * 64;  // [64][64]

    const int tid = threadIdx.x;
    const int ty = tid >> 4;
    const int tx = tid & 15;
    const int qt = (int)gridDim.x - 1 - (int)blockIdx.x;
    const int bh = blockIdx.y;
    const int b = bh >> 4;
    const int h = bh & 15;

    const float* Qg = qkv + ((size_t)b * TT + (size_t)qt * 128) * (3 * CC) + h * HD;
    const float* Kg = qkv + (size_t)b * TT * (3 * CC) + CC + h * HD;
    const float* Vg = Kg + CC;

    {
        const int r = tid >> 1;
        const int d0 = (tid & 1) << 5;
        const float* qp = Qg + (size_t)r * (3 * CC) + d0;
#pragma unroll
        for (int j = 0; j < 8; ++j) {
            float4 v = *(const float4*)(qp + j * 4);
            const int d = d0 + j * 4;
            sQT[(d + 0) * 128 + r] = v.x * 0.125f;
            sQT[(d + 1) * 128 + r] = v.y * 0.125f;
            sQT[(d + 2) * 128 + r] = v.z * 0.125f;
            sQT[(d + 3) * 128 + r] = v.w * 0.125f;
        }
    }

    float m_run[8], l_run[8], o[8][4];
#pragma unroll
    for (int i = 0; i < 8; ++i) {
        m_run[i] = -1e30f;
        l_run[i] = 0.f;
#pragma unroll
        for (int j = 0; j < 4; ++j) o[i][j] = 0.f;
    }

    const int nkt = 2 * qt + 2;
    for (int kt = 0; kt < nkt; ++kt) {
        __syncthreads();
        {
            const int r = tid >> 2;
            const int d0 = (tid & 3) << 4;
            const float* kp = Kg + (size_t)(kt * 64 + r) * (3 * CC) + d0;
            const float* vp = Vg + (size_t)(kt * 64 + r) * (3 * CC) + d0;
#pragma unroll
            for (int j = 0; j < 4; ++j) {
                float4 kv = *(const float4*)(kp + j * 4);
                const int d = d0 + j * 4;
                sKT[(d + 0) * 64 + r] = kv.x;
                sKT[(d + 1) * 64 + r] = kv.y;
                sKT[(d + 2) * 64 + r] = kv.z;
                sKT[(d + 3) * 64 + r] = kv.w;
                *(float4*)&sV[r * 64 + d0 + j * 4] = *(const float4*)(vp + j * 4);
            }
        }
        __syncthreads();

        float s[8][4];
#pragma unroll
        for (int i = 0; i < 8; ++i)
#pragma unroll
            for (int j = 0; j < 4; ++j) s[i][j] = 0.f;

#pragma unroll 8
        for (int d = 0; d < 64; ++d) {
            float q8[8], k4[4];
            *(float4*)&q8[0] = *(const float4*)&sQT[d * 128 + ty * 8];
            *(float4*)&q8[4] = *(const float4*)&sQT[d * 128 + ty * 8 + 4];
            *(float4*)&k4[0] = *(const float4*)&sKT[d * 64 + tx * 4];
#pragma unroll
            for (int i = 0; i < 8; ++i)
#pragma unroll
                for (int j = 0; j < 4; ++j)
                    s[i][j] = fmaf(q8[i], k4[j], s[i][j]);
        }

        if (kt >= 2 * qt) {
#pragma unroll
            for (int i = 0; i < 8; ++i) {
                const int qrow = qt * 128 + ty * 8 + i;
#pragma unroll
                for (int j = 0; j < 4; ++j) {
                    const int kcol = kt * 64 + tx * 4 + j;
                    if (kcol > qrow) s[i][j] = -1e30f;
                }
            }
        }

#pragma unroll
        for (int i = 0; i < 8; ++i) {
            float mx = fmaxf(fmaxf(s[i][0], s[i][1]), fmaxf(s[i][2], s[i][3]));
#pragma unroll
            for (int off = 1; off < 16; off <<= 1)
                mx = fmaxf(mx, __shfl_xor_sync(0xffffffffu, mx, off));
            const float mnew = fmaxf(m_run[i], mx);
            const float alpha = __expf(m_run[i] - mnew);
            float rs = 0.f;
#pragma unroll
            for (int j = 0; j < 4; ++j) {
                s[i][j] = __expf(s[i][j] - mnew);
                rs += s[i][j];
            }
#pragma unroll
            for (int off = 1; off < 16; off <<= 1)
                rs += __shfl_xor_sync(0xffffffffu, rs, off);
            m_run[i] = mnew;
            l_run[i] = l_run[i] * alpha + rs;
#pragma unroll
            for (int j = 0; j < 4; ++j) o[i][j] *= alpha;
        }

#pragma unroll
        for (int j = 0; j < 4; ++j) {
            float4 p0 = make_float4(s[0][j], s[1][j], s[2][j], s[3][j]);
            float4 p1 = make_float4(s[4][j], s[5][j], s[6][j], s[7][j]);
            *(float4*)&sPT[(tx * 4 + j) * 128 + ty * 8] = p0;
            *(float4*)&sPT[(tx * 4 + j) * 128 + ty * 8 + 4] = p1;
        }
        __syncthreads();

#pragma unroll 8
        for (int k = 0; k < 64; ++k) {
            float p8[8], v4[4];
            *(float4*)&p8[0] = *(const float4*)&sPT[k * 128 + ty * 8];
            *(float4*)&p8[4] = *(const float4*)&sPT[k * 128 + ty * 8 + 4];
            *(float4*)&v4[0] = *(const float4*)&sV[k * 64 + tx * 4];
#pragma unroll
            for (int i = 0; i < 8; ++i)
#pragma unroll
                for (int j = 0; j < 4; ++j)
                    o[i][j] = fmaf(p8[i], v4[j], o[i][j]);
        }
    }

#pragma unroll
    for (int i = 0; i < 8; ++i) {
        const float inv = 1.0f / l_run[i];
        const int row = qt * 128 + ty * 8 + i;
        float4 out = make_float4(o[i][0] * inv, o[i][1] * inv,
                                 o[i][2] * inv, o[i][3] * inv);
        *(float4*)&y[((size_t)b * TT + row) * CC + h * HD + tx * 4] = out;
    }
}

// ---------------------------------------------------------------------------
// launch
// ---------------------------------------------------------------------------
extern "C" void kernel_launch(void* const* d_in, const int* in_sizes, int n_in,
                              void* d_out, int out_size)
{
    (void)in_sizes; (void)n_in; (void)out_size;
    const float* x      = (const float*)d_in[0];
    const float* W_attn = (const float*)d_in[1];
    const float* b_attn = (const float*)d_in[2];
    const float* W_proj = (const float*)d_in[3];
    const float* b_proj = (const float*)d_in[4];
    float* out = (float*)d_out;

    float *qkv, *yb;
    __nv_bfloat16 *a3, *wa3, *wp3;
    cudaGetSymbolAddress((void**)&qkv, g_qkv);
    cudaGetSymbolAddress((void**)&yb, g_y);
    cudaGetSymbolAddress((void**)&a3, g_a3);
    cudaGetSymbolAddress((void**)&wa3, g_wa3);
    cudaGetSymbolAddress((void**)&wp3, g_wp3);

    cudaFuncSetAttribute(flash_attn_kernel,
                         cudaFuncAttributeMaxDynamicSharedMemorySize, 96 * 1024);
    cudaFuncSetAttribute(gemm_mma_kernel,
                         cudaFuncAttributeMaxDynamicSharedMemorySize,
                         NSTAGE * STAGE);

    // 0) split/transposes
    {
        const int n4 = MTOT * CC / 4;
        convert_split3_kernel<<<(n4 + 255) / 256, 256>>>(x, a3, n4);
        dim3 tb(32, 8);
        dim3 gb(3 * CC / 32, CC / 32);
        transpose_split3_kernel<<<gb, tb>>>(W_attn, wa3, CC, 3 * CC);
        dim3 gp(CC / 32, CC / 32);
        transpose_split3_kernel<<<gp, tb>>>(W_proj, wp3, CC, CC);
    }
    // 1) QKV = x @ W_attn + b_attn
    {
        dim3 grid(3 * CC / 128, MTOT / 128);  // (24, 32)
        gemm_mma_kernel<<<grid, 256, NSTAGE * STAGE>>>(a3, wa3, b_attn, qkv,
                                                       3 * CC);
    }
    // 2) attention (fp32)
    {
        dim3 grid(TT / 128, BB * NH);
        flash_attn_kernel<<<grid, 256, 96 * 1024>>>(qkv, yb);
    }
    // 3) out = y @ W_proj + b_proj
    {
        const int n4 = MTOT * CC / 4;
        convert_split3_kernel<<<(n4 + 255) / 256, 256>>>(yb, a3, n4);
        dim3 grid(CC / 128, MTOT / 128);  // (8, 32)
        gemm_mma_kernel<<<grid, 256, NSTAGE * STAGE>>>(a3, wp3, b_proj, out, CC);
    }
}

// round 5
// speedup vs baseline: 2.8235x; 2.0790x over previous
#include <cuda_runtime.h>
#include <cuda_bf16.h>
#include <cuda_fp16.h>
#include <cstdint>
#include <cstddef>

// ---------------------------------------------------------------------------
// MultiHeadAttention: x@W_attn+b -> causal MHA -> @W_proj+b
// B=2, T=2048, C=1024, H=16, D=64.
// Round 5: mma.sync everywhere. GEMMs: bf16 hi/lo split (K-tripled), 3-stage
// cp.async, 2 CTA/SM. Attention: split-bf16 QK^T + fp16 PV flash kernel.
// ---------------------------------------------------------------------------

#define BB 2
#define TT 2048
#define CC 1024
#define NH 16
#define HD 64
#define MTOT (BB * TT)  // 4096
#define K3 (3 * CC)     // 3072

// ------------------------------ scratch ------------------------------------
__device__ __nv_bfloat16 g_a3[MTOT * K3];       // [M][3K] act split [hi|hi|lo]
__device__ __nv_bfloat16 g_wa3[3 * CC * K3];    // W_attn^T [3C][3K] = [hi|lo|hi]
__device__ __nv_bfloat16 g_wp3[CC * K3];        // W_proj^T [C][3K]  = [hi|lo|hi]
__device__ __nv_bfloat16 g_qhi[BB * NH * TT * HD];  // Q/8 split, head-major
__device__ __nv_bfloat16 g_qlo[BB * NH * TT * HD];
__device__ __nv_bfloat16 g_khi[BB * NH * TT * HD];
__device__ __nv_bfloat16 g_klo[BB * NH * TT * HD];
__device__ __half        g_v[BB * NH * TT * HD];

// ------------------------------ helpers ------------------------------------
__device__ __forceinline__ uint32_t smem_u32(const void* p) {
    uint32_t a;
    asm("{ .reg .u64 t; cvta.to.shared.u64 t, %1; cvt.u32.u64 %0, t; }"
        : "=r"(a) : "l"(p));
    return a;
}
__device__ __forceinline__ uint32_t swz(uint32_t x) {  // SW128 (128B rows)
    return x ^ ((x >> 3) & 0x70);
}
__device__ __forceinline__ void cp16(uint32_t dst, const void* src) {
    asm volatile("cp.async.cg.shared.global [%0], [%1], 16;"
                 :: "r"(dst), "l"(src));
}
__device__ __forceinline__ void cp_commit() {
    asm volatile("cp.async.commit_group;");
}
template <int N>
__device__ __forceinline__ void cp_wait() {
    asm volatile("cp.async.wait_group %0;" :: "n"(N));
}
__device__ __forceinline__ void ldsm4(uint32_t& r0, uint32_t& r1, uint32_t& r2,
                                      uint32_t& r3, uint32_t addr) {
    asm volatile("ldmatrix.sync.aligned.m8n8.x4.shared.b16 {%0,%1,%2,%3}, [%4];"
                 : "=r"(r0), "=r"(r1), "=r"(r2), "=r"(r3) : "r"(addr));
}
__device__ __forceinline__ void ldsm4t(uint32_t& r0, uint32_t& r1, uint32_t& r2,
                                       uint32_t& r3, uint32_t addr) {
    asm volatile(
        "ldmatrix.sync.aligned.m8n8.x4.trans.shared.b16 {%0,%1,%2,%3}, [%4];"
        : "=r"(r0), "=r"(r1), "=r"(r2), "=r"(r3) : "r"(addr));
}
__device__ __forceinline__ void mma_bf16(float* c, const uint32_t* a,
                                         const uint32_t* b) {
    asm volatile(
        "mma.sync.aligned.m16n8k16.row.col.f32.bf16.bf16.f32 "
        "{%0,%1,%2,%3}, {%4,%5,%6,%7}, {%8,%9}, {%0,%1,%2,%3};"
        : "+f"(c[0]), "+f"(c[1]), "+f"(c[2]), "+f"(c[3])
        : "r"(a[0]), "r"(a[1]), "r"(a[2]), "r"(a[3]), "r"(b[0]), "r"(b[1]));
}
__device__ __forceinline__ void mma_f16(float* c, const uint32_t* a,
                                        const uint32_t* b) {
    asm volatile(
        "mma.sync.aligned.m16n8k16.row.col.f32.f16.f16.f32 "
        "{%0,%1,%2,%3}, {%4,%5,%6,%7}, {%8,%9}, {%0,%1,%2,%3};"
        : "+f"(c[0]), "+f"(c[1]), "+f"(c[2]), "+f"(c[3])
        : "r"(a[0]), "r"(a[1]), "r"(a[2]), "r"(a[3]), "r"(b[0]), "r"(b[1]));
}
__device__ __forceinline__ uint32_t packh2(float a, float b) {
    __half2 h = __floats2half2_rn(a, b);
    return *reinterpret_cast<uint32_t*>(&h);
}

// ---------------------------------------------------------------------------
// convert_split3: X [M][K] fp32 -> A3 [M][3K] bf16 = [hi | hi | lo]
// ---------------------------------------------------------------------------
__global__ __launch_bounds__(256) void convert_split3_kernel(
    const float* __restrict__ X, __nv_bfloat16* __restrict__ A3, int n4)
{
    int i = blockIdx.x * blockDim.x + threadIdx.x;
    if (i >= n4) return;
    const int m = i >> 8;
    const int kk = (i & 255) << 2;
    float4 v = ((const float4*)X)[i];
    float vv[4] = {v.x, v.y, v.z, v.w};
    __nv_bfloat16 h[4], l[4];
#pragma unroll
    for (int j = 0; j < 4; ++j) {
        h[j] = __float2bfloat16(vv[j]);
        l[j] = __float2bfloat16(vv[j] - __bfloat162float(h[j]));
    }
    __nv_bfloat162 h0(h[0], h[1]), h1(h[2], h[3]);
    __nv_bfloat162 l0(l[0], l[1]), l1(l[2], l[3]);
    __nv_bfloat162* p0 = (__nv_bfloat162*)(A3 + (size_t)m * K3 + kk);
    p0[0] = h0; p0[1] = h1;
    __nv_bfloat162* p1 = (__nv_bfloat162*)(A3 + (size_t)m * K3 + CC + kk);
    p1[0] = h0; p1[1] = h1;
    __nv_bfloat162* p2 = (__nv_bfloat162*)(A3 + (size_t)m * K3 + 2 * CC + kk);
    p2[0] = l0; p2[1] = l1;
}

// ---------------------------------------------------------------------------
// transpose_split3: W [K][N] fp32 -> B3 [N][3K] bf16 = [hi | lo | hi]
// ---------------------------------------------------------------------------
__global__ __launch_bounds__(256) void transpose_split3_kernel(
    const float* __restrict__ W, __nv_bfloat16* __restrict__ B3, int K, int N)
{
    __shared__ float t[32][33];
    const int n0 = blockIdx.x * 32, k0 = blockIdx.y * 32;
    const int tx = threadIdx.x, ty = threadIdx.y;
#pragma unroll
    for (int i = 0; i < 32; i += 8)
        t[ty + i][tx] = W[(size_t)(k0 + ty + i) * N + n0 + tx];
    __syncthreads();
#pragma unroll
    for (int i = 0; i < 32; i += 8) {
        const int n = n0 + ty + i, k = k0 + tx;
        const float v = t[tx][ty + i];
        const __nv_bfloat16 h = __float2bfloat16(v);
        const __nv_bfloat16 l = __float2bfloat16(v - __bfloat162float(h));
        __nv_bfloat16* row = B3 + (size_t)n * (3 * K);
        row[k] = h;
        row[K + k] = l;
        row[2 * K + k] = h;
    }
}

// ---------------------------------------------------------------------------
// mma.sync bf16 GEMM: C = A3 @ B3^T (+bias). CTA 128x128, BK=64, 3 stages.
// EPI=0: fp32 out + bias.  EPI=1: QKV epilogue -> split Q/K (bf16) + V (fp16),
// head-major [b*16+h][t][d], Q pre-scaled by 0.125.
// ---------------------------------------------------------------------------
#define BKB 128
#define TILE_A 16384
#define STAGE 32768
#define NSTAGE 3

template <int EPI>
__global__ __launch_bounds__(256, 2) void gemm_mma_kernel(
    const __nv_bfloat16* __restrict__ A3, const __nv_bfloat16* __restrict__ B3,
    const float* __restrict__ bias, float* __restrict__ Cout,
    __nv_bfloat16* __restrict__ Qhi, __nv_bfloat16* __restrict__ Qlo,
    __nv_bfloat16* __restrict__ Khi, __nv_bfloat16* __restrict__ Klo,
    __half* __restrict__ Vh, int N)
{
    extern __shared__ char dsm[];
    const uint32_t sbase = smem_u32(dsm);

    const int tid = threadIdx.x;
    const int lane = tid & 31;
    const int warp = tid >> 5;
    const int wm = warp >> 2;
    const int wn = warp & 3;
    const int n0 = blockIdx.x * 128;
    const int m0 = blockIdx.y * 128;

    const int ldrow = tid >> 1;
    const int cgrp = (tid & 1) * 4;
    const __nv_bfloat16* aRow = A3 + (size_t)(m0 + ldrow) * K3 + cgrp * 8;
    const __nv_bfloat16* bRow = B3 + (size_t)(n0 + ldrow) * K3 + cgrp * 8;
    uint32_t dstOff[4];
#pragma unroll
    for (int j = 0; j < 4; ++j)
        dstOff[j] = swz(ldrow * BKB + (cgrp + j) * 16);

    const int NCH = K3 / 64;  // 48

#pragma unroll
    for (int c = 0; c < NSTAGE - 1; ++c) {
        const uint32_t sA = sbase + c * STAGE;
        const uint32_t sB = sA + TILE_A;
#pragma unroll
        for (int j = 0; j < 4; ++j) {
            cp16(sA + dstOff[j], aRow + c * 64 + j * 8);
            cp16(sB + dstOff[j], bRow + c * 64 + j * 8);
        }
        cp_commit();
    }

    float acc[4][4][4];
#pragma unroll
    for (int i = 0; i < 4; ++i)
#pragma unroll
        for (int j = 0; j < 4; ++j)
#pragma unroll
            for (int r = 0; r < 4; ++r) acc[i][j][r] = 0.f;

    const int arow = wm * 64 + (lane & 15);
    const uint32_t acolbase = (lane >> 4) << 4;
    const int brow = wn * 32 + ((lane >> 4) << 3) + (lane & 7);
    const uint32_t bcolbase = ((lane >> 3) & 1) << 4;

    for (int c = 0; c < NCH; ++c) {
        cp_wait<NSTAGE - 2>();
        __syncthreads();

        if (c + NSTAGE - 1 < NCH) {
            const int cc = c + NSTAGE - 1;
            const int s = cc % NSTAGE;
            const uint32_t sA = sbase + s * STAGE;
            const uint32_t sB = sA + TILE_A;
#pragma unroll
            for (int j = 0; j < 4; ++j) {
                cp16(sA + dstOff[j], aRow + cc * 64 + j * 8);
                cp16(sB + dstOff[j], bRow + cc * 64 + j * 8);
            }
        }
        cp_commit();

        const int s = c % NSTAGE;
        const uint32_t sA = sbase + s * STAGE;
        const uint32_t sB = sA + TILE_A;

#pragma unroll
        for (int kk = 0; kk < 4; ++kk) {
            uint32_t af[4][4], bf[2][4];
#pragma unroll
            for (int fm = 0; fm < 4; ++fm) {
                const int r = arow + fm * 16;
                const uint32_t addr =
                    sA + swz((uint32_t)r * BKB + kk * 32 + acolbase);
                ldsm4(af[fm][0], af[fm][1], af[fm][2], af[fm][3], addr);
            }
#pragma unroll
            for (int fn2 = 0; fn2 < 2; ++fn2) {
                const int r = brow + fn2 * 16;
                const uint32_t addr =
                    sB + swz((uint32_t)r * BKB + kk * 32 + bcolbase);
                ldsm4(bf[fn2][0], bf[fn2][1], bf[fn2][2], bf[fn2][3], addr);
            }
#pragma unroll
            for (int fm = 0; fm < 4; ++fm)
#pragma unroll
                for (int fn = 0; fn < 4; ++fn)
                    mma_bf16(acc[fm][fn], af[fm], &bf[fn >> 1][(fn & 1) * 2]);
        }
        __syncthreads();
    }

    // epilogue
#pragma unroll
    for (int fm = 0; fm < 4; ++fm) {
        const int r0 = m0 + wm * 64 + fm * 16 + (lane >> 2);
#pragma unroll
        for (int fn = 0; fn < 4; ++fn) {
            const int cidx = n0 + wn * 32 + fn * 8 + (lane & 3) * 2;
            const float b0 = bias[cidx], b1 = bias[cidx + 1];
            float v00 = acc[fm][fn][0] + b0, v01 = acc[fm][fn][1] + b1;
            float v10 = acc[fm][fn][2] + b0, v11 = acc[fm][fn][3] + b1;
            if (EPI == 0) {
                *(float2*)&Cout[(size_t)r0 * N + cidx] = make_float2(v00, v01);
                *(float2*)&Cout[(size_t)(r0 + 8) * N + cidx] =
                    make_float2(v10, v11);
            } else {
                const int reg = cidx >> 10;
                const int idx = cidx & 1023;
                const int h = idx >> 6, d = idx & 63;
#pragma unroll
                for (int rr = 0; rr < 2; ++rr) {
                    const int m = r0 + rr * 8;
                    const int bb = m >> 11, t = m & 2047;
                    float va = rr ? v10 : v00;
                    float vb = rr ? v11 : v01;
                    const size_t off =
                        ((size_t)(bb * NH + h) * TT + t) * HD + d;
                    if (reg == 0) {
                        va *= 0.125f; vb *= 0.125f;
                        __nv_bfloat16 ha = __float2bfloat16(va);
                        __nv_bfloat16 hb = __float2bfloat16(vb);
                        *(__nv_bfloat162*)&Qhi[off] = __nv_bfloat162(ha, hb);
                        *(__nv_bfloat162*)&Qlo[off] = __nv_bfloat162(
                            __float2bfloat16(va - __bfloat162float(ha)),
                            __float2bfloat16(vb - __bfloat162float(hb)));
                    } else if (reg == 1) {
                        __nv_bfloat16 ha = __float2bfloat16(va);
                        __nv_bfloat16 hb = __float2bfloat16(vb);
                        *(__nv_bfloat162*)&Khi[off] = __nv_bfloat162(ha, hb);
                        *(__nv_bfloat162*)&Klo[off] = __nv_bfloat162(
                            __float2bfloat16(va - __bfloat162float(ha)),
                            __float2bfloat16(vb - __bfloat162float(hb)));
                    } else {
                        *(__half2*)&Vh[off] = __floats2half2_rn(va, vb);
                    }
                }
            }
        }
    }
}

// ---------------------------------------------------------------------------
// Flash attention on mma.sync.
// CTA: 128 queries x one (b,h). 8 warps; warp = 16 q rows x full 64-key tile.
// S = (Qhi+Qlo)(Khi+Klo)^T 3-term bf16 split; P,V in fp16 for PV.
// smem: Qhi(16K)|Qlo(16K)| 2 stages x [Khi 8K|Klo 8K|V 8K].
// Output written directly as split a3 [M][3K] for the proj GEMM.
// ---------------------------------------------------------------------------
#define AQHI 0
#define AQLO 16384
#define ASTG 32768
#define STGB 24576
#define ATT_SMEM (ASTG + 2 * STGB + 1024)

__global__ __launch_bounds__(256) void attn_mma_kernel(
    const __nv_bfloat16* __restrict__ Qhi, const __nv_bfloat16* __restrict__ Qlo,
    const __nv_bfloat16* __restrict__ Khi, const __nv_bfloat16* __restrict__ Klo,
    const __half* __restrict__ V, __nv_bfloat16* __restrict__ A3out)
{
    extern __shared__ char dsm[];
    const uint32_t dbase = smem_u32(dsm);
    const uint32_t sb = (dbase + 1023) & ~1023u;

    const int tid = threadIdx.x;
    const int lane = tid & 31;
    const int w = tid >> 5;
    const int qt = (int)gridDim.x - 1 - (int)blockIdx.x;
    const int bh = blockIdx.y;  // b*16+h

    const size_t headbase = (size_t)bh * TT * HD;
    const __nv_bfloat16* Qhig = Qhi + headbase + (size_t)qt * 128 * HD;
    const __nv_bfloat16* Qlog = Qlo + headbase + (size_t)qt * 128 * HD;
    const __nv_bfloat16* Khig = Khi + headbase;
    const __nv_bfloat16* Klog = Klo + headbase;
    const __half* Vg = V + headbase;

    // prologue: Q (both halves) + tile 0, one group
#pragma unroll
    for (int i = 0; i < 4; ++i) {
        const int c = tid + i * 256;  // 1024 chunks per matrix
        const int row = c >> 3, cu = c & 7;
        const uint32_t so = swz(row * 128 + cu * 16);
        cp16(sb + AQHI + so, Qhig + row * HD + cu * 8);
        cp16(sb + AQLO + so, Qlog + row * HD + cu * 8);
    }
    {
        const uint32_t stg = sb + ASTG;
#pragma unroll
        for (int i = 0; i < 2; ++i) {
            const int c = tid + i * 256;  // 512 chunks per matrix
            const int row = c >> 3, cu = c & 7;
            const uint32_t so = swz(row * 128 + cu * 16);
            const size_t go = (size_t)row * HD + cu * 8;
            cp16(stg + so, Khig + go);
            cp16(stg + 8192 + so, Klog + go);
            cp16(stg + 16384 + so, Vg + go);
        }
    }
    cp_commit();

    float oc[8][4];
#pragma unroll
    for (int f = 0; f < 8; ++f)
#pragma unroll
        for (int r = 0; r < 4; ++r) oc[f][r] = 0.f;
    float m0 = -1e30f, m1 = -1e30f, l0 = 0.f, l1 = 0.f;

    const uint32_t aBase = (uint32_t)((w * 16 + (lane & 15)) * 128 +
                                      ((lane >> 4) << 4));
    const uint32_t bRow = ((lane >> 4) << 3) + (lane & 7);
    const uint32_t bColB = ((lane >> 3) & 1) << 4;
    const uint32_t vRow = (((lane >> 3) & 1) << 3) + (lane & 7);
    const uint32_t vColB = (lane >> 4) << 4;

    const int nkt = 2 * qt + 2;
    for (int kt = 0; kt < nkt; ++kt) {
        if (kt + 1 < nkt) {  // prefetch next tile
            const uint32_t stg = sb + ASTG + ((kt + 1) & 1) * STGB;
            const size_t kbase = (size_t)(kt + 1) * 64 * HD;
#pragma unroll
            for (int i = 0; i < 2; ++i) {
                const int c = tid + i * 256;
                const int row = c >> 3, cu = c & 7;
                const uint32_t so = swz(row * 128 + cu * 16);
                const size_t go = kbase + (size_t)row * HD + cu * 8;
                cp16(stg + so, Khig + go);
                cp16(stg + 8192 + so, Klog + go);
                cp16(stg + 16384 + so, Vg + go);
            }
        }
        cp_commit();
        cp_wait<1>();
        __syncthreads();

        const uint32_t stg = sb + ASTG + (kt & 1) * STGB;

        // ---- S = Q K^T (3-term split) ----
        float sc[8][4];
#pragma unroll
        for (int f = 0; f < 8; ++f)
#pragma unroll
            for (int r = 0; r < 4; ++r) sc[f][r] = 0.f;

#pragma unroll
        for (int kk = 0; kk < 4; ++kk) {  // Khi x (Qhi, Qlo)
            uint32_t bk[4][4];
#pragma unroll
            for (int g = 0; g < 4; ++g)
                ldsm4(bk[g][0], bk[g][1], bk[g][2], bk[g][3],
                      stg + swz((g * 16 + bRow) * 128 + kk * 32 + bColB));
            uint32_t aq[4];
            ldsm4(aq[0], aq[1], aq[2], aq[3], sb + AQHI + swz(aBase + kk * 32));
#pragma unroll
            for (int f = 0; f < 8; ++f)
                mma_bf16(sc[f], aq, &bk[f >> 1][(f & 1) * 2]);
            ldsm4(aq[0], aq[1], aq[2], aq[3], sb + AQLO + swz(aBase + kk * 32));
#pragma unroll
            for (int f = 0; f < 8; ++f)
                mma_bf16(sc[f], aq, &bk[f >> 1][(f & 1) * 2]);
        }
#pragma unroll
        for (int kk = 0; kk < 4; ++kk) {  // Klo x Qhi
            uint32_t bk[4][4];
#pragma unroll
            for (int g = 0; g < 4; ++g)
                ldsm4(bk[g][0], bk[g][1], bk[g][2], bk[g][3],
                      stg + 8192 +
                          swz((g * 16 + bRow) * 128 + kk * 32 + bColB));
            uint32_t aq[4];
            ldsm4(aq[0], aq[1], aq[2], aq[3], sb + AQHI + swz(aBase + kk * 32));
#pragma unroll
            for (int f = 0; f < 8; ++f)
                mma_bf16(sc[f], aq, &bk[f >> 1][(f & 1) * 2]);
        }

        // ---- causal mask (diagonal-region tiles) ----
        if (kt >= 2 * qt) {
            const int rq = qt * 128 + w * 16 + (lane >> 2);
#pragma unroll
            for (int f = 0; f < 8; ++f) {
                const int cg = kt * 64 + f * 8 + 2 * (lane & 3);
                if (cg > rq) sc[f][0] = -1e30f;
                if (cg + 1 > rq) sc[f][1] = -1e30f;
                if (cg > rq + 8) sc[f][2] = -1e30f;
                if (cg + 1 > rq + 8) sc[f][3] = -1e30f;
            }
        }

        // ---- online softmax (rows r, r+8; 4-lane shuffle reductions) ----
        float mx0 = -1e30f, mx1 = -1e30f;
#pragma unroll
        for (int f = 0; f < 8; ++f) {
            mx0 = fmaxf(mx0, fmaxf(sc[f][0], sc[f][1]));
            mx1 = fmaxf(mx1, fmaxf(sc[f][2], sc[f][3]));
        }
        mx0 = fmaxf(mx0, __shfl_xor_sync(0xffffffffu, mx0, 1));
        mx0 = fmaxf(mx0, __shfl_xor_sync(0xffffffffu, mx0, 2));
        mx1 = fmaxf(mx1, __shfl_xor_sync(0xffffffffu, mx1, 1));
        mx1 = fmaxf(mx1, __shfl_xor_sync(0xffffffffu, mx1, 2));
        const float mn0 = fmaxf(m0, mx0), mn1 = fmaxf(m1, mx1);
        const float al0 = __expf(m0 - mn0), al1 = __expf(m1 - mn1);
        float rs0 = 0.f, rs1 = 0.f;
#pragma unroll
        for (int f = 0; f < 8; ++f) {
            sc[f][0] = __expf(sc[f][0] - mn0);
            sc[f][1] = __expf(sc[f][1] - mn0);
            sc[f][2] = __expf(sc[f][2] - mn1);
            sc[f][3] = __expf(sc[f][3] - mn1);
            rs0 += sc[f][0] + sc[f][1];
            rs1 += sc[f][2] + sc[f][3];
        }
        rs0 += __shfl_xor_sync(0xffffffffu, rs0, 1);
        rs0 += __shfl_xor_sync(0xffffffffu, rs0, 2);
        rs1 += __shfl_xor_sync(0xffffffffu, rs1, 1);
        rs1 += __shfl_xor_sync(0xffffffffu, rs1, 2);
        m0 = mn0; m1 = mn1;
        l0 = l0 * al0 + rs0;
        l1 = l1 * al1 + rs1;
#pragma unroll
        for (int f = 0; f < 8; ++f) {
            oc[f][0] *= al0; oc[f][1] *= al0;
            oc[f][2] *= al1; oc[f][3] *= al1;
        }

        // ---- P (fp16, registers) ----
        uint32_t pa[4][4];
#pragma unroll
        for (int j = 0; j < 4; ++j) {
            pa[j][0] = packh2(sc[2 * j][0], sc[2 * j][1]);
            pa[j][1] = packh2(sc[2 * j][2], sc[2 * j][3]);
            pa[j][2] = packh2(sc[2 * j + 1][0], sc[2 * j + 1][1]);
            pa[j][3] = packh2(sc[2 * j + 1][2], sc[2 * j + 1][3]);
        }

        // ---- O += P V ----
#pragma unroll
        for (int kb = 0; kb < 4; ++kb) {
            uint32_t bv[4][4];
#pragma unroll
            for (int g = 0; g < 4; ++g)
                ldsm4t(bv[g][0], bv[g][1], bv[g][2], bv[g][3],
                       stg + 16384 +
                           swz((kb * 16 + vRow) * 128 + g * 32 + vColB));
#pragma unroll
            for (int f = 0; f < 8; ++f)
                mma_f16(oc[f], pa[kb], &bv[f >> 1][(f & 1) * 2]);
        }
        __syncthreads();
    }

    // ---- epilogue: write split a3 [M][3K] = [hi|hi|lo] ----
    const float inv0 = 1.f / l0, inv1 = 1.f / l1;
    const int b = bh >> 4, h = bh & 15;
    const int t0 = qt * 128 + w * 16 + (lane >> 2);
    const size_t mr0 = (size_t)(b * TT + t0) * K3;
    const size_t mr1 = mr0 + (size_t)8 * K3;
#pragma unroll
    for (int f = 0; f < 8; ++f) {
        const int n = h * HD + f * 8 + 2 * (lane & 3);
#pragma unroll
        for (int rr = 0; rr < 2; ++rr) {
            const size_t base = rr ? mr1 : mr0;
            const float va = (rr ? oc[f][2] * inv1 : oc[f][0] * inv0);
            const float vb = (rr ? oc[f][3] * inv1 : oc[f][1] * inv0);
            __nv_bfloat16 ha = __float2bfloat16(va);
            __nv_bfloat16 hb = __float2bfloat16(vb);
            __nv_bfloat162 hp(ha, hb);
            __nv_bfloat162 lp(__float2bfloat16(va - __bfloat162float(ha)),
                              __float2bfloat16(vb - __bfloat162float(hb)));
            *(__nv_bfloat162*)&A3out[base + n] = hp;
            *(__nv_bfloat162*)&A3out[base + CC + n] = hp;
            *(__nv_bfloat162*)&A3out[base + 2 * CC + n] = lp;
        }
    }
}

// ---------------------------------------------------------------------------
// launch
// ---------------------------------------------------------------------------
extern "C" void kernel_launch(void* const* d_in, const int* in_sizes, int n_in,
                              void* d_out, int out_size)
{
    (void)in_sizes; (void)n_in; (void)out_size;
    const float* x      = (const float*)d_in[0];
    const float* W_attn = (const float*)d_in[1];
    const float* b_attn = (const float*)d_in[2];
    const float* W_proj = (const float*)d_in[3];
    const float* b_proj = (const float*)d_in[4];
    float* out = (float*)d_out;

    __nv_bfloat16 *a3, *wa3, *wp3, *qhi, *qlo, *khi, *klo;
    __half* vh;
    cudaGetSymbolAddress((void**)&a3, g_a3);
    cudaGetSymbolAddress((void**)&wa3, g_wa3);
    cudaGetSymbolAddress((void**)&wp3, g_wp3);
    cudaGetSymbolAddress((void**)&qhi, g_qhi);
    cudaGetSymbolAddress((void**)&qlo, g_qlo);
    cudaGetSymbolAddress((void**)&khi, g_khi);
    cudaGetSymbolAddress((void**)&klo, g_klo);
    cudaGetSymbolAddress((void**)&vh, g_v);

    cudaFuncSetAttribute(gemm_mma_kernel<0>,
                         cudaFuncAttributeMaxDynamicSharedMemorySize,
                         NSTAGE * STAGE);
    cudaFuncSetAttribute(gemm_mma_kernel<1>,
                         cudaFuncAttributeMaxDynamicSharedMemorySize,
                         NSTAGE * STAGE);
    cudaFuncSetAttribute(attn_mma_kernel,
                         cudaFuncAttributeMaxDynamicSharedMemorySize, ATT_SMEM);

    // 0) splits
    {
        const int n4 = MTOT * CC / 4;
        convert_split3_kernel<<<(n4 + 255) / 256, 256>>>(x, a3, n4);
        dim3 tb(32, 8);
        dim3 gb(3 * CC / 32, CC / 32);
        transpose_split3_kernel<<<gb, tb>>>(W_attn, wa3, CC, 3 * CC);
        dim3 gp(CC / 32, CC / 32);
        transpose_split3_kernel<<<gp, tb>>>(W_proj, wp3, CC, CC);
    }
    // 1) QKV GEMM -> split Q/K (bf16) + V (fp16), head-major
    {
        dim3 grid(3 * CC / 128, MTOT / 128);
        gemm_mma_kernel<1><<<grid, 256, NSTAGE * STAGE>>>(
            a3, wa3, b_attn, nullptr, qhi, qlo, khi, klo, vh, 3 * CC);
    }
    // 2) attention -> writes split a3 directly
    {
        dim3 grid(TT / 128, BB * NH);
        attn_mma_kernel<<<grid, 256, ATT_SMEM>>>(qhi, qlo, khi, klo, vh, a3);
    }
    // 3) out = y @ W_proj + b_proj
    {
        dim3 grid(CC / 128, MTOT / 128);
        gemm_mma_kernel<0><<<grid, 256, NSTAGE * STAGE>>>(
            a3, wp3, b_proj, out, nullptr, nullptr, nullptr, nullptr, nullptr,
            CC);
    }
}

// round 6
// speedup vs baseline: 2.9470x; 1.0437x over previous
#include <cuda_runtime.h>
#include <cuda_bf16.h>
#include <cuda_fp16.h>
#include <cstdint>
#include <cstddef>

// ---------------------------------------------------------------------------
// MultiHeadAttention: x@W_attn+b -> causal MHA -> @W_proj+b
// B=2, T=2048, C=1024, H=16, D=64.
// Round 6: GEMM1 bf16 3-term split (K-tripled); attention split-bf16 QK^T +
// fp16 PV; GEMM2 fp16 2-term split (K-doubled). mma.sync throughout.
// ---------------------------------------------------------------------------

#define BB 2
#define TT 2048
#define CC 1024
#define NH 16
#define HD 64
#define MTOT (BB * TT)  // 4096
#define K3 (3 * CC)     // 3072 (GEMM1 split K)
#define K2 (2 * CC)     // 2048 (GEMM2 split K)

// ------------------------------ scratch ------------------------------------
__device__ __nv_bfloat16 g_a3[MTOT * K3];       // GEMM1 A [M][3K]=[hi|hi|lo];
                                                // reused as fp16 [M][2K]=[y|y]
__device__ __nv_bfloat16 g_wa3[3 * CC * K3];    // W_attn^T [3C][3K]=[hi|lo|hi]
__device__ __half        g_wp2[CC * K2];        // W_proj^T [C][2K]=[hi|lo] fp16
__device__ __nv_bfloat16 g_qhi[BB * NH * TT * HD];
__device__ __nv_bfloat16 g_qlo[BB * NH * TT * HD];
__device__ __nv_bfloat16 g_khi[BB * NH * TT * HD];
__device__ __nv_bfloat16 g_klo[BB * NH * TT * HD];
__device__ __half        g_v[BB * NH * TT * HD];

// ------------------------------ helpers ------------------------------------
__device__ __forceinline__ uint32_t smem_u32(const void* p) {
    uint32_t a;
    asm("{ .reg .u64 t; cvta.to.shared.u64 t, %1; cvt.u32.u64 %0, t; }"
        : "=r"(a) : "l"(p));
    return a;
}
__device__ __forceinline__ uint32_t swz(uint32_t x) {  // SW128 (128B rows)
    return x ^ ((x >> 3) & 0x70);
}
__device__ __forceinline__ void cp16(uint32_t dst, const void* src) {
    asm volatile("cp.async.cg.shared.global [%0], [%1], 16;"
                 :: "r"(dst), "l"(src));
}
__device__ __forceinline__ void cp_commit() {
    asm volatile("cp.async.commit_group;");
}
template <int N>
__device__ __forceinline__ void cp_wait() {
    asm volatile("cp.async.wait_group %0;" :: "n"(N));
}
__device__ __forceinline__ void ldsm4(uint32_t& r0, uint32_t& r1, uint32_t& r2,
                                      uint32_t& r3, uint32_t addr) {
    asm volatile("ldmatrix.sync.aligned.m8n8.x4.shared.b16 {%0,%1,%2,%3}, [%4];"
                 : "=r"(r0), "=r"(r1), "=r"(r2), "=r"(r3) : "r"(addr));
}
__device__ __forceinline__ void ldsm4t(uint32_t& r0, uint32_t& r1, uint32_t& r2,
                                       uint32_t& r3, uint32_t addr) {
    asm volatile(
        "ldmatrix.sync.aligned.m8n8.x4.trans.shared.b16 {%0,%1,%2,%3}, [%4];"
        : "=r"(r0), "=r"(r1), "=r"(r2), "=r"(r3) : "r"(addr));
}
__device__ __forceinline__ void mma_bf16(float* c, const uint32_t* a,
                                         const uint32_t* b) {
    asm volatile(
        "mma.sync.aligned.m16n8k16.row.col.f32.bf16.bf16.f32 "
        "{%0,%1,%2,%3}, {%4,%5,%6,%7}, {%8,%9}, {%0,%1,%2,%3};"
        : "+f"(c[0]), "+f"(c[1]), "+f"(c[2]), "+f"(c[3])
        : "r"(a[0]), "r"(a[1]), "r"(a[2]), "r"(a[3]), "r"(b[0]), "r"(b[1]));
}
__device__ __forceinline__ void mma_f16(float* c, const uint32_t* a,
                                        const uint32_t* b) {
    asm volatile(
        "mma.sync.aligned.m16n8k16.row.col.f32.f16.f16.f32 "
        "{%0,%1,%2,%3}, {%4,%5,%6,%7}, {%8,%9}, {%0,%1,%2,%3};"
        : "+f"(c[0]), "+f"(c[1]), "+f"(c[2]), "+f"(c[3])
        : "r"(a[0]), "r"(a[1]), "r"(a[2]), "r"(a[3]), "r"(b[0]), "r"(b[1]));
}
__device__ __forceinline__ uint32_t packh2(float a, float b) {
    __half2 h = __floats2half2_rn(a, b);
    return *reinterpret_cast<uint32_t*>(&h);
}

// ---------------------------------------------------------------------------
// convert_split3: X [M][K] fp32 -> A3 [M][3K] bf16 = [hi | hi | lo]
// ---------------------------------------------------------------------------
__global__ __launch_bounds__(256) void convert_split3_kernel(
    const float* __restrict__ X, __nv_bfloat16* __restrict__ A3, int n4)
{
    int i = blockIdx.x * blockDim.x + threadIdx.x;
    if (i >= n4) return;
    const int m = i >> 8;
    const int kk = (i & 255) << 2;
    float4 v = ((const float4*)X)[i];
    float vv[4] = {v.x, v.y, v.z, v.w};
    __nv_bfloat16 h[4], l[4];
#pragma unroll
    for (int j = 0; j < 4; ++j) {
        h[j] = __float2bfloat16(vv[j]);
        l[j] = __float2bfloat16(vv[j] - __bfloat162float(h[j]));
    }
    __nv_bfloat162 h0(h[0], h[1]), h1(h[2], h[3]);
    __nv_bfloat162 l0(l[0], l[1]), l1(l[2], l[3]);
    __nv_bfloat162* p0 = (__nv_bfloat162*)(A3 + (size_t)m * K3 + kk);
    p0[0] = h0; p0[1] = h1;
    __nv_bfloat162* p1 = (__nv_bfloat162*)(A3 + (size_t)m * K3 + CC + kk);
    p1[0] = h0; p1[1] = h1;
    __nv_bfloat162* p2 = (__nv_bfloat162*)(A3 + (size_t)m * K3 + 2 * CC + kk);
    p2[0] = l0; p2[1] = l1;
}

// ---------------------------------------------------------------------------
// transpose_split3: W [K][N] fp32 -> B3 [N][3K] bf16 = [hi | lo | hi]
// ---------------------------------------------------------------------------
__global__ __launch_bounds__(256) void transpose_split3_kernel(
    const float* __restrict__ W, __nv_bfloat16* __restrict__ B3, int K, int N)
{
    __shared__ float t[32][33];
    const int n0 = blockIdx.x * 32, k0 = blockIdx.y * 32;
    const int tx = threadIdx.x, ty = threadIdx.y;
#pragma unroll
    for (int i = 0; i < 32; i += 8)
        t[ty + i][tx] = W[(size_t)(k0 + ty + i) * N + n0 + tx];
    __syncthreads();
#pragma unroll
    for (int i = 0; i < 32; i += 8) {
        const int n = n0 + ty + i, k = k0 + tx;
        const float v = t[tx][ty + i];
        const __nv_bfloat16 h = __float2bfloat16(v);
        const __nv_bfloat16 l = __float2bfloat16(v - __bfloat162float(h));
        __nv_bfloat16* row = B3 + (size_t)n * (3 * K);
        row[k] = h;
        row[K + k] = l;
        row[2 * K + k] = h;
    }
}

// ---------------------------------------------------------------------------
// transpose_split2_f16: W [K][N] fp32 -> B2 [N][2K] fp16 = [hi | lo]
// ---------------------------------------------------------------------------
__global__ __launch_bounds__(256) void transpose_split2_f16_kernel(
    const float* __restrict__ W, __half* __restrict__ B2, int K, int N)
{
    __shared__ float t[32][33];
    const int n0 = blockIdx.x * 32, k0 = blockIdx.y * 32;
    const int tx = threadIdx.x, ty = threadIdx.y;
#pragma unroll
    for (int i = 0; i < 32; i += 8)
        t[ty + i][tx] = W[(size_t)(k0 + ty + i) * N + n0 + tx];
    __syncthreads();
#pragma unroll
    for (int i = 0; i < 32; i += 8) {
        const int n = n0 + ty + i, k = k0 + tx;
        const float v = t[tx][ty + i];
        const __half h = __float2half_rn(v);
        const __half l = __float2half_rn(v - __half2float(h));
        __half* row = B2 + (size_t)n * (2 * K);
        row[k] = h;
        row[K + k] = l;
    }
}

// ---------------------------------------------------------------------------
// mma.sync GEMM: C = A @ B^T (+bias). CTA 128x128, BK=64, 3 stages, 2 CTA/SM.
// F16=0: bf16 operands. F16=1: fp16 operands.
// EPI=0: fp32 out + bias. EPI=1: QKV epilogue -> split Q/K bf16 + V fp16,
//        head-major, Q pre-scaled by 0.125.
// ---------------------------------------------------------------------------
#define BKB 128
#define TILE_A 16384
#define STAGE 32768
#define NSTAGE 3

template <int EPI, int F16>
__global__ __launch_bounds__(256, 2) void gemm_mma_kernel(
    const uint16_t* __restrict__ A, const uint16_t* __restrict__ B,
    const float* __restrict__ bias, float* __restrict__ Cout,
    __nv_bfloat16* __restrict__ Qhi, __nv_bfloat16* __restrict__ Qlo,
    __nv_bfloat16* __restrict__ Khi, __nv_bfloat16* __restrict__ Klo,
    __half* __restrict__ Vh, int N, int Klen)
{
    extern __shared__ char dsm[];
    const uint32_t sbase = smem_u32(dsm);

    const int tid = threadIdx.x;
    const int lane = tid & 31;
    const int warp = tid >> 5;
    const int wm = warp >> 2;
    const int wn = warp & 3;
    const int n0 = blockIdx.x * 128;
    const int m0 = blockIdx.y * 128;

    const int ldrow = tid >> 1;
    const int cgrp = (tid & 1) * 4;
    const uint16_t* aRow = A + (size_t)(m0 + ldrow) * Klen + cgrp * 8;
    const uint16_t* bRow = B + (size_t)(n0 + ldrow) * Klen + cgrp * 8;
    uint32_t dstOff[4];
#pragma unroll
    for (int j = 0; j < 4; ++j)
        dstOff[j] = swz(ldrow * BKB + (cgrp + j) * 16);

    const int NCH = Klen / 64;

#pragma unroll
    for (int c = 0; c < NSTAGE - 1; ++c) {
        const uint32_t sA = sbase + c * STAGE;
        const uint32_t sB = sA + TILE_A;
#pragma unroll
        for (int j = 0; j < 4; ++j) {
            cp16(sA + dstOff[j], aRow + c * 64 + j * 8);
            cp16(sB + dstOff[j], bRow + c * 64 + j * 8);
        }
        cp_commit();
    }

    float acc[4][4][4];
#pragma unroll
    for (int i = 0; i < 4; ++i)
#pragma unroll
        for (int j = 0; j < 4; ++j)
#pragma unroll
            for (int r = 0; r < 4; ++r) acc[i][j][r] = 0.f;

    const int arow = wm * 64 + (lane & 15);
    const uint32_t acolbase = (lane >> 4) << 4;
    const int brow = wn * 32 + ((lane >> 4) << 3) + (lane & 7);
    const uint32_t bcolbase = ((lane >> 3) & 1) << 4;

    for (int c = 0; c < NCH; ++c) {
        cp_wait<NSTAGE - 2>();
        __syncthreads();  // single barrier per chunk (trailing one removed)

        if (c + NSTAGE - 1 < NCH) {
            const int cc = c + NSTAGE - 1;
            const int s = cc % NSTAGE;
            const uint32_t sA = sbase + s * STAGE;
            const uint32_t sB = sA + TILE_A;
#pragma unroll
            for (int j = 0; j < 4; ++j) {
                cp16(sA + dstOff[j], aRow + (size_t)cc * 64 + j * 8);
                cp16(sB + dstOff[j], bRow + (size_t)cc * 64 + j * 8);
            }
        }
        cp_commit();

        const int s = c % NSTAGE;
        const uint32_t sA = sbase + s * STAGE;
        const uint32_t sB = sA + TILE_A;

#pragma unroll
        for (int kk = 0; kk < 4; ++kk) {
            uint32_t af[4][4], bf[2][4];
#pragma unroll
            for (int fm = 0; fm < 4; ++fm) {
                const int r = arow + fm * 16;
                const uint32_t addr =
                    sA + swz((uint32_t)r * BKB + kk * 32 + acolbase);
                ldsm4(af[fm][0], af[fm][1], af[fm][2], af[fm][3], addr);
            }
#pragma unroll
            for (int fn2 = 0; fn2 < 2; ++fn2) {
                const int r = brow + fn2 * 16;
                const uint32_t addr =
                    sB + swz((uint32_t)r * BKB + kk * 32 + bcolbase);
                ldsm4(bf[fn2][0], bf[fn2][1], bf[fn2][2], bf[fn2][3], addr);
            }
#pragma unroll
            for (int fm = 0; fm < 4; ++fm)
#pragma unroll
                for (int fn = 0; fn < 4; ++fn) {
                    if (F16)
                        mma_f16(acc[fm][fn], af[fm], &bf[fn >> 1][(fn & 1) * 2]);
                    else
                        mma_bf16(acc[fm][fn], af[fm], &bf[fn >> 1][(fn & 1) * 2]);
                }
        }
        __syncthreads();
    }

    // epilogue
#pragma unroll
    for (int fm = 0; fm < 4; ++fm) {
        const int r0 = m0 + wm * 64 + fm * 16 + (lane >> 2);
#pragma unroll
        for (int fn = 0; fn < 4; ++fn) {
            const int cidx = n0 + wn * 32 + fn * 8 + (lane & 3) * 2;
            const float b0 = bias[cidx], b1 = bias[cidx + 1];
            float v00 = acc[fm][fn][0] + b0, v01 = acc[fm][fn][1] + b1;
            float v10 = acc[fm][fn][2] + b0, v11 = acc[fm][fn][3] + b1;
            if (EPI == 0) {
                *(float2*)&Cout[(size_t)r0 * N + cidx] = make_float2(v00, v01);
                *(float2*)&Cout[(size_t)(r0 + 8) * N + cidx] =
                    make_float2(v10, v11);
            } else {
                const int reg = cidx >> 10;
                const int idx = cidx & 1023;
                const int h = idx >> 6, d = idx & 63;
#pragma unroll
                for (int rr = 0; rr < 2; ++rr) {
                    const int m = r0 + rr * 8;
                    const int bb = m >> 11, t = m & 2047;
                    float va = rr ? v10 : v00;
                    float vb = rr ? v11 : v01;
                    const size_t off =
                        ((size_t)(bb * NH + h) * TT + t) * HD + d;
                    if (reg == 0) {
                        va *= 0.125f; vb *= 0.125f;
                        __nv_bfloat16 ha = __float2bfloat16(va);
                        __nv_bfloat16 hb = __float2bfloat16(vb);
                        *(__nv_bfloat162*)&Qhi[off] = __nv_bfloat162(ha, hb);
                        *(__nv_bfloat162*)&Qlo[off] = __nv_bfloat162(
                            __float2bfloat16(va - __bfloat162float(ha)),
                            __float2bfloat16(vb - __bfloat162float(hb)));
                    } else if (reg == 1) {
                        __nv_bfloat16 ha = __float2bfloat16(va);
                        __nv_bfloat16 hb = __float2bfloat16(vb);
                        *(__nv_bfloat162*)&Khi[off] = __nv_bfloat162(ha, hb);
                        *(__nv_bfloat162*)&Klo[off] = __nv_bfloat162(
                            __float2bfloat16(va - __bfloat162float(ha)),
                            __float2bfloat16(vb - __bfloat162float(hb)));
                    } else {
                        *(__half2*)&Vh[off] = __floats2half2_rn(va, vb);
                    }
                }
            }
        }
    }
}

// ---------------------------------------------------------------------------
// Flash attention on mma.sync (as round 5) — epilogue now writes y as fp16
// [M][2K] = [y | y] for the fp16 2-term proj GEMM.
// ---------------------------------------------------------------------------
#define AQHI 0
#define AQLO 16384
#define ASTG 32768
#define STGB 24576
#define ATT_SMEM (ASTG + 2 * STGB + 1024)

__global__ __launch_bounds__(256) void attn_mma_kernel(
    const __nv_bfloat16* __restrict__ Qhi, const __nv_bfloat16* __restrict__ Qlo,
    const __nv_bfloat16* __restrict__ Khi, const __nv_bfloat16* __restrict__ Klo,
    const __half* __restrict__ V, __half* __restrict__ Y2)
{
    extern __shared__ char dsm[];
    const uint32_t dbase = smem_u32(dsm);
    const uint32_t sb = (dbase + 1023) & ~1023u;

    const int tid = threadIdx.x;
    const int lane = tid & 31;
    const int w = tid >> 5;
    const int qt = (int)gridDim.x - 1 - (int)blockIdx.x;
    const int bh = blockIdx.y;

    const size_t headbase = (size_t)bh * TT * HD;
    const __nv_bfloat16* Qhig = Qhi + headbase + (size_t)qt * 128 * HD;
    const __nv_bfloat16* Qlog = Qlo + headbase + (size_t)qt * 128 * HD;
    const __nv_bfloat16* Khig = Khi + headbase;
    const __nv_bfloat16* Klog = Klo + headbase;
    const __half* Vg = V + headbase;

#pragma unroll
    for (int i = 0; i < 4; ++i) {
        const int c = tid + i * 256;
        const int row = c >> 3, cu = c & 7;
        const uint32_t so = swz(row * 128 + cu * 16);
        cp16(sb + AQHI + so, Qhig + row * HD + cu * 8);
        cp16(sb + AQLO + so, Qlog + row * HD + cu * 8);
    }
    {
        const uint32_t stg = sb + ASTG;
#pragma unroll
        for (int i = 0; i < 2; ++i) {
            const int c = tid + i * 256;
            const int row = c >> 3, cu = c & 7;
            const uint32_t so = swz(row * 128 + cu * 16);
            const size_t go = (size_t)row * HD + cu * 8;
            cp16(stg + so, Khig + go);
            cp16(stg + 8192 + so, Klog + go);
            cp16(stg + 16384 + so, Vg + go);
        }
    }
    cp_commit();

    float oc[8][4];
#pragma unroll
    for (int f = 0; f < 8; ++f)
#pragma unroll
        for (int r = 0; r < 4; ++r) oc[f][r] = 0.f;
    float m0 = -1e30f, m1 = -1e30f, l0 = 0.f, l1 = 0.f;

    const uint32_t aBase = (uint32_t)((w * 16 + (lane & 15)) * 128 +
                                      ((lane >> 4) << 4));
    const uint32_t bRow = ((lane >> 4) << 3) + (lane & 7);
    const uint32_t bColB = ((lane >> 3) & 1) << 4;
    const uint32_t vRow = (((lane >> 3) & 1) << 3) + (lane & 7);
    const uint32_t vColB = (lane >> 4) << 4;

    const int nkt = 2 * qt + 2;
    for (int kt = 0; kt < nkt; ++kt) {
        if (kt + 1 < nkt) {
            const uint32_t stg = sb + ASTG + ((kt + 1) & 1) * STGB;
            const size_t kbase = (size_t)(kt + 1) * 64 * HD;
#pragma unroll
            for (int i = 0; i < 2; ++i) {
                const int c = tid + i * 256;
                const int row = c >> 3, cu = c & 7;
                const uint32_t so = swz(row * 128 + cu * 16);
                const size_t go = kbase + (size_t)row * HD + cu * 8;
                cp16(stg + so, Khig + go);
                cp16(stg + 8192 + so, Klog + go);
                cp16(stg + 16384 + so, Vg + go);
            }
        }
        cp_commit();
        cp_wait<1>();
        __syncthreads();

        const uint32_t stg = sb + ASTG + (kt & 1) * STGB;

        float sc[8][4];
#pragma unroll
        for (int f = 0; f < 8; ++f)
#pragma unroll
            for (int r = 0; r < 4; ++r) sc[f][r] = 0.f;

#pragma unroll
        for (int kk = 0; kk < 4; ++kk) {
            uint32_t bk[4][4];
#pragma unroll
            for (int g = 0; g < 4; ++g)
                ldsm4(bk[g][0], bk[g][1], bk[g][2], bk[g][3],
                      stg + swz((g * 16 + bRow) * 128 + kk * 32 + bColB));
            uint32_t aq[4];
            ldsm4(aq[0], aq[1], aq[2], aq[3], sb + AQHI + swz(aBase + kk * 32));
#pragma unroll
            for (int f = 0; f < 8; ++f)
                mma_bf16(sc[f], aq, &bk[f >> 1][(f & 1) * 2]);
            ldsm4(aq[0], aq[1], aq[2], aq[3], sb + AQLO + swz(aBase + kk * 32));
#pragma unroll
            for (int f = 0; f < 8; ++f)
                mma_bf16(sc[f], aq, &bk[f >> 1][(f & 1) * 2]);
        }
#pragma unroll
        for (int kk = 0; kk < 4; ++kk) {
            uint32_t bk[4][4];
#pragma unroll
            for (int g = 0; g < 4; ++g)
                ldsm4(bk[g][0], bk[g][1], bk[g][2], bk[g][3],
                      stg + 8192 +
                          swz((g * 16 + bRow) * 128 + kk * 32 + bColB));
            uint32_t aq[4];
            ldsm4(aq[0], aq[1], aq[2], aq[3], sb + AQHI + swz(aBase + kk * 32));
#pragma unroll
            for (int f = 0; f < 8; ++f)
                mma_bf16(sc[f], aq, &bk[f >> 1][(f & 1) * 2]);
        }

        if (kt >= 2 * qt) {
            const int rq = qt * 128 + w * 16 + (lane >> 2);
#pragma unroll
            for (int f = 0; f < 8; ++f) {
                const int cg = kt * 64 + f * 8 + 2 * (lane & 3);
                if (cg > rq) sc[f][0] = -1e30f;
                if (cg + 1 > rq) sc[f][1] = -1e30f;
                if (cg > rq + 8) sc[f][2] = -1e30f;
                if (cg + 1 > rq + 8) sc[f][3] = -1e30f;
            }
        }

        float mx0 = -1e30f, mx1 = -1e30f;
#pragma unroll
        for (int f = 0; f < 8; ++f) {
            mx0 = fmaxf(mx0, fmaxf(sc[f][0], sc[f][1]));
            mx1 = fmaxf(mx1, fmaxf(sc[f][2], sc[f][3]));
        }
        mx0 = fmaxf(mx0, __shfl_xor_sync(0xffffffffu, mx0, 1));
        mx0 = fmaxf(mx0, __shfl_xor_sync(0xffffffffu, mx0, 2));
        mx1 = fmaxf(mx1, __shfl_xor_sync(0xffffffffu, mx1, 1));
        mx1 = fmaxf(mx1, __shfl_xor_sync(0xffffffffu, mx1, 2));
        const float mn0 = fmaxf(m0, mx0), mn1 = fmaxf(m1, mx1);
        const float al0 = __expf(m0 - mn0), al1 = __expf(m1 - mn1);
        float rs0 = 0.f, rs1 = 0.f;
#pragma unroll
        for (int f = 0; f < 8; ++f) {
            sc[f][0] = __expf(sc[f][0] - mn0);
            sc[f][1] = __expf(sc[f][1] - mn0);
            sc[f][2] = __expf(sc[f][2] - mn1);
            sc[f][3] = __expf(sc[f][3] - mn1);
            rs0 += sc[f][0] + sc[f][1];
            rs1 += sc[f][2] + sc[f][3];
        }
        rs0 += __shfl_xor_sync(0xffffffffu, rs0, 1);
        rs0 += __shfl_xor_sync(0xffffffffu, rs0, 2);
        rs1 += __shfl_xor_sync(0xffffffffu, rs1, 1);
        rs1 += __shfl_xor_sync(0xffffffffu, rs1, 2);
        m0 = mn0; m1 = mn1;
        l0 = l0 * al0 + rs0;
        l1 = l1 * al1 + rs1;
#pragma unroll
        for (int f = 0; f < 8; ++f) {
            oc[f][0] *= al0; oc[f][1] *= al0;
            oc[f][2] *= al1; oc[f][3] *= al1;
        }

        uint32_t pa[4][4];
#pragma unroll
        for (int j = 0; j < 4; ++j) {
            pa[j][0] = packh2(sc[2 * j][0], sc[2 * j][1]);
            pa[j][1] = packh2(sc[2 * j][2], sc[2 * j][3]);
            pa[j][2] = packh2(sc[2 * j + 1][0], sc[2 * j + 1][1]);
            pa[j][3] = packh2(sc[2 * j + 1][2], sc[2 * j + 1][3]);
        }

#pragma unroll
        for (int kb = 0; kb < 4; ++kb) {
            uint32_t bv[4][4];
#pragma unroll
            for (int g = 0; g < 4; ++g)
                ldsm4t(bv[g][0], bv[g][1], bv[g][2], bv[g][3],
                       stg + 16384 +
                           swz((kb * 16 + vRow) * 128 + g * 32 + vColB));
#pragma unroll
            for (int f = 0; f < 8; ++f)
                mma_f16(oc[f], pa[kb], &bv[f >> 1][(f & 1) * 2]);
        }
        __syncthreads();
    }

    // ---- epilogue: write y fp16 [M][2K] = [y | y] ----
    const float inv0 = 1.f / l0, inv1 = 1.f / l1;
    const int b = bh >> 4, h = bh & 15;
    const int t0 = qt * 128 + w * 16 + (lane >> 2);
    const size_t mr0 = (size_t)(b * TT + t0) * K2;
    const size_t mr1 = mr0 + (size_t)8 * K2;
#pragma unroll
    for (int f = 0; f < 8; ++f) {
        const int n = h * HD + f * 8 + 2 * (lane & 3);
#pragma unroll
        for (int rr = 0; rr < 2; ++rr) {
            const size_t base = rr ? mr1 : mr0;
            const float va = (rr ? oc[f][2] * inv1 : oc[f][0] * inv0);
            const float vb = (rr ? oc[f][3] * inv1 : oc[f][1] * inv0);
            __half2 hp = __floats2half2_rn(va, vb);
            *(__half2*)&Y2[base + n] = hp;
            *(__half2*)&Y2[base + CC + n] = hp;
        }
    }
}

// ---------------------------------------------------------------------------
// launch
// ---------------------------------------------------------------------------
extern "C" void kernel_launch(void* const* d_in, const int* in_sizes, int n_in,
                              void* d_out, int out_size)
{
    (void)in_sizes; (void)n_in; (void)out_size;
    const float* x      = (const float*)d_in[0];
    const float* W_attn = (const float*)d_in[1];
    const float* b_attn = (const float*)d_in[2];
    const float* W_proj = (const float*)d_in[3];
    const float* b_proj = (const float*)d_in[4];
    float* out = (float*)d_out;

    __nv_bfloat16 *a3, *wa3, *qhi, *qlo, *khi, *klo;
    __half *wp2, *vh;
    cudaGetSymbolAddress((void**)&a3, g_a3);
    cudaGetSymbolAddress((void**)&wa3, g_wa3);
    cudaGetSymbolAddress((void**)&wp2, g_wp2);
    cudaGetSymbolAddress((void**)&qhi, g_qhi);
    cudaGetSymbolAddress((void**)&qlo, g_qlo);
    cudaGetSymbolAddress((void**)&khi, g_khi);
    cudaGetSymbolAddress((void**)&klo, g_klo);
    cudaGetSymbolAddress((void**)&vh, g_v);

    cudaFuncSetAttribute(gemm_mma_kernel<1, 0>,
                         cudaFuncAttributeMaxDynamicSharedMemorySize,
                         NSTAGE * STAGE);
    cudaFuncSetAttribute(gemm_mma_kernel<0, 1>,
                         cudaFuncAttributeMaxDynamicSharedMemorySize,
                         NSTAGE * STAGE);
    cudaFuncSetAttribute(attn_mma_kernel,
                         cudaFuncAttributeMaxDynamicSharedMemorySize, ATT_SMEM);

    // 0) splits
    {
        const int n4 = MTOT * CC / 4;
        convert_split3_kernel<<<(n4 + 255) / 256, 256>>>(x, a3, n4);
        dim3 tb(32, 8);
        dim3 gb(3 * CC / 32, CC / 32);
        transpose_split3_kernel<<<gb, tb>>>(W_attn, wa3, CC, 3 * CC);
        dim3 gp(CC / 32, CC / 32);
        transpose_split2_f16_kernel<<<gp, tb>>>(W_proj, wp2, CC, CC);
    }
    // 1) QKV GEMM (bf16 3-term) -> split Q/K + V, head-major
    {
        dim3 grid(3 * CC / 128, MTOT / 128);
        gemm_mma_kernel<1, 0><<<grid, 256, NSTAGE * STAGE>>>(
            (const uint16_t*)a3, (const uint16_t*)wa3, b_attn, nullptr,
            qhi, qlo, khi, klo, vh, 3 * CC, K3);
    }
    // 2) attention -> writes y fp16 [M][2K] (reusing g_a3 storage)
    {
        dim3 grid(TT / 128, BB * NH);
        attn_mma_kernel<<<grid, 256, ATT_SMEM>>>(qhi, qlo, khi, klo, vh,
                                                 (__half*)a3);
    }
    // 3) out = y @ W_proj + b_proj (fp16 2-term)
    {
        dim3 grid(CC / 128, MTOT / 128);
        gemm_mma_kernel<0, 1><<<grid, 256, NSTAGE * STAGE>>>(
            (const uint16_t*)a3, (const uint16_t*)wp2, b_proj, out,
            nullptr, nullptr, nullptr, nullptr, nullptr, CC, K2);
    }
}